// round 8
// baseline (speedup 1.0000x reference)
#include <cuda_runtime.h>
#include <math.h>

// B=32, T=128, I=512, H=512, L=2, O=512
// Scratch (static __device__ globals: allowed)
__device__ float g_xh[4096 * 1024];   // input proj zr, row m=b*128+t
__device__ float g_xr[4096 * 512];    // input proj r-gate input
__device__ float g_out1[4096 * 512];  // layer-1 fwd outputs
__device__ float g_out2[4096 * 512];  // layer-2 fwd outputs (unused tail)
__device__ float g_h[2 * 16384];      // h double buffer, layout (k, b)
__device__ float g_hr1[32 * 512];     // reverse step1 hidden (b, j)
__device__ float g_hr2T[512 * 32];    // reverse step2 hidden (j, b)
__device__ unsigned g_bar;

__global__ void init_kernel() {
    unsigned tid = blockIdx.x * blockDim.x + threadIdx.x;
    if (tid == 0) g_bar = 0u;
    for (unsigned i = tid; i < 32768u; i += gridDim.x * blockDim.x) g_h[i] = 0.f;
}

__global__ void zero_h_kernel() {
    unsigned tid = blockIdx.x * blockDim.x + threadIdx.x;
    for (unsigned i = tid; i < 16384u; i += gridDim.x * blockDim.x) g_h[i] = 0.f;
}

// C(4096,N) = A(4096,512) @ W(512,N) + bias.  A row m=b*128+t is contiguous
// in both x (B,T,I) and g_out1. dst_sel: 0 -> g_xh, 1 -> g_xr.
__global__ void __launch_bounds__(256) bulk_gemm(
    const float* __restrict__ Aext, int src_sel,
    const float* __restrict__ W, const float* __restrict__ bias,
    int N, int dst_sel)
{
    __shared__ float As[16][136];
    __shared__ float Bs[16][136];
    const float* A = src_sel ? g_out1 : Aext;
    float* dst = dst_sel ? g_xr : g_xh;

    float acc[8][8];
#pragma unroll
    for (int i = 0; i < 8; i++)
#pragma unroll
        for (int j = 0; j < 8; j++) acc[i][j] = 0.f;

    int tid = threadIdx.x, tx = tid & 15, ty = tid >> 4;
    int row0 = blockIdx.y * 128, col0 = blockIdx.x * 128;

    for (int k0 = 0; k0 < 512; k0 += 16) {
#pragma unroll
        for (int i = 0; i < 2; i++) {              // A tile: 128 x 16
            int t = tid + i * 256;
            int r = t >> 2, kq = (t & 3) << 2;
            float4 v = *(const float4*)&A[(size_t)(row0 + r) * 512 + k0 + kq];
            As[kq + 0][r] = v.x; As[kq + 1][r] = v.y;
            As[kq + 2][r] = v.z; As[kq + 3][r] = v.w;
        }
#pragma unroll
        for (int i = 0; i < 2; i++) {              // B tile: 16 x 128
            int t = tid + i * 256;
            int kr = t >> 5, nq = (t & 31) << 2;
            *(float4*)&Bs[kr][nq] = *(const float4*)&W[(size_t)(k0 + kr) * N + col0 + nq];
        }
        __syncthreads();
#pragma unroll
        for (int kk = 0; kk < 16; kk++) {
            float a[8], b[8];
            *(float4*)&a[0] = *(float4*)&As[kk][ty * 8];
            *(float4*)&a[4] = *(float4*)&As[kk][ty * 8 + 4];
            *(float4*)&b[0] = *(float4*)&Bs[kk][tx * 8];
            *(float4*)&b[4] = *(float4*)&Bs[kk][tx * 8 + 4];
#pragma unroll
            for (int i = 0; i < 8; i++)
#pragma unroll
                for (int j = 0; j < 8; j++) acc[i][j] += a[i] * b[j];
        }
        __syncthreads();
    }
#pragma unroll
    for (int i = 0; i < 8; i++) {
        int row = row0 + ty * 8 + i;
#pragma unroll
        for (int j = 0; j < 8; j++) {
            int col = col0 + tx * 8 + j;
            dst[(size_t)row * N + col] = acc[i][j] + __ldg(&bias[col]);
        }
    }
}

// Persistent forward GRU scan: 128 blocks x 256 threads, block owns 4 h-cols.
// SMEM floats: hs 16384 | swz/swr/swg 3*2048 | red 3104 | sb 16  = 25648
#define SCAN_SMEM_BYTES (25648 * 4)

__global__ void __launch_bounds__(256) scan_kernel(
    int layer, int bar_base,
    const float* __restrict__ Whh, const float* __restrict__ bhh,
    const float* __restrict__ Whr, const float* __restrict__ bhr)
{
    extern __shared__ float sm[];
    float* hs  = sm;
    float* swz = hs + 16384;
    float* swr = swz + 2048;
    float* swg = swr + 2048;
    float* red = swg + 2048;
    float* sb  = red + 3104;

    const int tid = threadIdx.x;
    const int j0 = blockIdx.x * 4;

    // persistent recurrent weights, interleaved [k*4 + jl] (conflict-free LDS)
    for (int i = tid; i < 2048; i += 256) {
        int k = i >> 2, jl = i & 3;
        swz[i] = Whh[k * 1024 + j0 + jl];
        swr[i] = Whh[k * 1024 + 512 + j0 + jl];
        swg[i] = Whr[k * 512 + j0 + jl];
    }
    if (tid < 4) {
        sb[tid]     = bhh[j0 + tid];
        sb[4 + tid] = bhh[512 + j0 + tid];
        sb[8 + tid] = bhr[j0 + tid];
    }
    __syncthreads();

    const float* xh = g_xh;
    const float* xr = g_xr;
    float* out = layer ? g_out2 : g_out1;

    const int ks = tid >> 5;          // K-group (64 k each)
    const int combo = tid & 31;       // jl(4) x bg(8)
    const int jl = combo >> 3, bg = combo & 7;
    const int kbase = ks * 64;
    float4* hs4 = (float4*)hs;

    for (int t = 0; t < 128; t++) {
        const float4* hc4 = (const float4*)(g_h + (t & 1) * 16384);
        float* hnxt = g_h + ((t + 1) & 1) * 16384;

        // stage h (must bypass L1: buffers reused every 2 steps)
        for (int i = tid; i < 4096; i += 256) hs4[i] = __ldcg(hc4 + i);
        __syncthreads();

        float az0=0,az1=0,az2=0,az3=0, ar0=0,ar1=0,ar2=0,ar3=0;
        float ag0=0,ag1=0,ag2=0,ag3=0;
#pragma unroll 8
        for (int k = 0; k < 64; k++) {
            int kg = kbase + k;
            float wzv = swz[kg * 4 + jl];
            float wrv = swr[kg * 4 + jl];
            float wgv = swg[kg * 4 + jl];
            float4 h4 = hs4[kg * 8 + bg];
            az0 += h4.x*wzv; az1 += h4.y*wzv; az2 += h4.z*wzv; az3 += h4.w*wzv;
            ar0 += h4.x*wrv; ar1 += h4.y*wrv; ar2 += h4.z*wrv; ar3 += h4.w*wrv;
            ag0 += h4.x*wgv; ag1 += h4.y*wgv; ag2 += h4.z*wgv; ag3 += h4.w*wgv;
        }
        float* rp = red + combo * 97 + ks * 12;
        rp[0]=az0; rp[1]=az1; rp[2]=az2;  rp[3]=az3;
        rp[4]=ar0; rp[5]=ar1; rp[6]=ar2;  rp[7]=ar3;
        rp[8]=ag0; rp[9]=ag1; rp[10]=ag2; rp[11]=ag3;
        __syncthreads();

        if (tid < 128) {
            int c = tid >> 2, i = tid & 3;
            int jl2 = c >> 3, bg2 = c & 7;
            int j = j0 + jl2, b = bg2 * 4 + i;
            const float* q = red + c * 97;
            float z = 0.f, r = 0.f, g = 0.f;
#pragma unroll
            for (int s = 0; s < 8; s++) {
                z += q[s * 12 + i];
                r += q[s * 12 + 4 + i];
                g += q[s * 12 + 8 + i];
            }
            int m = b * 128 + t;
            z += __ldg(&xh[(size_t)m * 1024 + j]) + sb[jl2];
            r += __ldg(&xh[(size_t)m * 1024 + 512 + j]) + sb[4 + jl2];
            float zs = 1.f / (1.f + __expf(-z));
            float rs = 1.f / (1.f + __expf(-r));
            float gg = tanhf((g + sb[8 + jl2]) * rs + __ldg(&xr[(size_t)m * 512 + j]));
            float hold = hs[j * 32 + b];
            float hnew = zs * hold + (1.f - zs) * gg;
            hnxt[j * 32 + b] = hnew;
            out[(size_t)m * 512 + j] = hnew;
        }

        // grid barrier (all 128 blocks co-resident)
        __threadfence();
        __syncthreads();
        if (tid == 0) {
            atomicAdd(&g_bar, 1u);
            unsigned need = (unsigned)bar_base + (unsigned)(t + 1) * 128u;
            while (*((volatile unsigned*)&g_bar) < need) { }
            __threadfence();
        }
        __syncthreads();
    }
}

// One GRU step with h=0:
//   z = sig(x@Wxh[:, :H] + bxh_z + bhh_z); r = sig(x@Wxh[:, H:] + bxh_r + bhh_r)
//   h = (1-z) * tanh(bhr*r + x@Wxr + bxr)
__global__ void __launch_bounds__(512) rev_step(
    const float* __restrict__ Xext, int ldx, int src_sel,
    const float* __restrict__ Wxh, const float* __restrict__ bxh,
    const float* __restrict__ bhh,
    const float* __restrict__ Wxr, const float* __restrict__ bxr,
    const float* __restrict__ bhr, int dst_trans)
{
    __shared__ float xs[256 * 33];
    const float* X = src_sel ? g_hr1 : Xext;
    int tid = threadIdx.x;
    int jl = tid >> 5, b = tid & 31;
    int j = blockIdx.x * 16 + jl;
    float az = 0.f, ar = 0.f, ag = 0.f;

    for (int k0 = 0; k0 < 512; k0 += 256) {
        __syncthreads();
        int half = tid >> 8, kl = tid & 255;
        for (int b2 = half; b2 < 32; b2 += 2)
            xs[kl * 33 + b2] = X[(size_t)b2 * ldx + k0 + kl];
        __syncthreads();
#pragma unroll 8
        for (int k = 0; k < 256; k++) {
            float xv = xs[k * 33 + b];
            int kk = k0 + k;
            az += xv * __ldg(&Wxh[(size_t)kk * 1024 + j]);
            ar += xv * __ldg(&Wxh[(size_t)kk * 1024 + 512 + j]);
            ag += xv * __ldg(&Wxr[(size_t)kk * 512 + j]);
        }
    }
    float z = 1.f / (1.f + __expf(-(az + __ldg(&bxh[j]) + __ldg(&bhh[j]))));
    float r = 1.f / (1.f + __expf(-(ar + __ldg(&bxh[512 + j]) + __ldg(&bhh[512 + j]))));
    float g = tanhf(__ldg(&bhr[j]) * r + ag + __ldg(&bxr[j]));
    float h = (1.f - z) * g;
    if (dst_trans) g_hr2T[j * 32 + b] = h;
    else           g_hr1[b * 512 + j] = h;
}

// out(32,512) = [h_fwd_final | hr2] (32,1024) @ Wfc + bfc
// h_fwd_final lives in g_h buffer 0 (layout (k,b)); hr2 in g_hr2T (j,b).
__global__ void __launch_bounds__(512) fc_kernel(
    const float* __restrict__ Wfc, const float* __restrict__ bfc,
    float* __restrict__ out)
{
    int tid = threadIdx.x;
    int jl = tid >> 5, b = tid & 31;
    int j = blockIdx.x * 16 + jl;
    float acc = 0.f;
#pragma unroll 4
    for (int k = 0; k < 512; k++)
        acc += g_h[k * 32 + b] * __ldg(&Wfc[(size_t)k * 512 + j]);
#pragma unroll 4
    for (int k = 0; k < 512; k++)
        acc += g_hr2T[k * 32 + b] * __ldg(&Wfc[(size_t)(512 + k) * 512 + j]);
    out[b * 512 + j] = acc + __ldg(&bfc[j]);
}

extern "C" void kernel_launch(void* const* d_in, const int* in_sizes, int n_in,
                              void* d_out, int out_size) {
    const float* x   = (const float*)d_in[0];
    const float* Wxh = (const float*)d_in[1];
    const float* bxh = (const float*)d_in[2];
    const float* Whh = (const float*)d_in[3];
    const float* bhh = (const float*)d_in[4];
    const float* Wxr = (const float*)d_in[5];
    const float* bxr = (const float*)d_in[6];
    const float* Whr = (const float*)d_in[7];
    const float* bhr = (const float*)d_in[8];
    const float* Wfc = (const float*)d_in[9];
    const float* bfc = (const float*)d_in[10];
    float* out = (float*)d_out;

    cudaFuncSetAttribute(scan_kernel,
        cudaFuncAttributeMaxDynamicSharedMemorySize, SCAN_SMEM_BYTES);

    const size_t WH = 512 * 1024, WR = 512 * 512;  // per (l,d) slab sizes

    init_kernel<<<64, 256>>>();

    // layer 0 forward (l=0, d=0 -> slab 0)
    dim3 g1(8, 32), g2(4, 32);
    bulk_gemm<<<g1, 256>>>(x, 0, Wxh, bxh, 1024, 0);
    bulk_gemm<<<g2, 256>>>(x, 0, Wxr, bxr, 512, 1);
    scan_kernel<<<128, 256, SCAN_SMEM_BYTES>>>(0, 0, Whh, bhh, Whr, bhr);

    // layer 1 forward (l=1, d=0 -> slab 2)
    zero_h_kernel<<<16, 256>>>();
    bulk_gemm<<<g1, 256>>>(nullptr, 1, Wxh + 2 * WH, bxh + 2 * 1024, 1024, 0);
    bulk_gemm<<<g2, 256>>>(nullptr, 1, Wxr + 2 * WR, bxr + 2 * 512, 512, 1);
    scan_kernel<<<128, 256, SCAN_SMEM_BYTES>>>(1, 16384,
        Whh + 2 * WH, bhh + 2 * 1024, Whr + 2 * WR, bhr + 2 * 512);

    // reverse branch: two single steps (l=0,d=1 -> slab 1; l=1,d=1 -> slab 3)
    rev_step<<<32, 512>>>(x + 127 * 512, 128 * 512, 0,
        Wxh + 1 * WH, bxh + 1 * 1024, bhh + 1 * 1024,
        Wxr + 1 * WR, bxr + 1 * 512, bhr + 1 * 512, 0);
    rev_step<<<32, 512>>>(nullptr, 512, 1,
        Wxh + 3 * WH, bxh + 3 * 1024, bhh + 3 * 1024,
        Wxr + 3 * WR, bxr + 3 * 512, bhr + 3 * 512, 1);

    fc_kernel<<<32, 512>>>(Wfc, bfc, out);
}

// round 9
// speedup vs baseline: 1.0572x; 1.0572x over previous
#include <cuda_runtime.h>
#include <math.h>

// B=32, T=128, I=512, H=512, L=2, O=512
__device__ float g_xh[4096 * 1024];   // input proj zr, row m=b*128+t
__device__ float g_xr[4096 * 512];    // input proj r-gate input
__device__ float g_out1[4096 * 512];  // layer-1 fwd outputs
__device__ float g_h[2 * 16384];      // h double buffer, layout (j, b)
__device__ float g_hr1[32 * 512];     // reverse step1 hidden (b, j)
__device__ float g_hr2T[512 * 32];    // reverse step2 hidden (j, b)
__device__ unsigned g_bar;

__global__ void init_kernel() {
    unsigned tid = blockIdx.x * blockDim.x + threadIdx.x;
    if (tid == 0) g_bar = 0u;
    for (unsigned i = tid; i < 32768u; i += gridDim.x * blockDim.x) g_h[i] = 0.f;
}

__global__ void zero_h_kernel() {
    unsigned tid = blockIdx.x * blockDim.x + threadIdx.x;
    for (unsigned i = tid; i < 16384u; i += gridDim.x * blockDim.x) g_h[i] = 0.f;
}

// C(4096,N) = A(4096,512) @ W(512,N) + bias. (unchanged from R8 — near SIMT peak)
__global__ void __launch_bounds__(256) bulk_gemm(
    const float* __restrict__ Aext, int src_sel,
    const float* __restrict__ W, const float* __restrict__ bias,
    int N, int dst_sel)
{
    __shared__ float As[16][136];
    __shared__ float Bs[16][136];
    const float* A = src_sel ? g_out1 : Aext;
    float* dst = dst_sel ? g_xr : g_xh;

    float acc[8][8];
#pragma unroll
    for (int i = 0; i < 8; i++)
#pragma unroll
        for (int j = 0; j < 8; j++) acc[i][j] = 0.f;

    int tid = threadIdx.x, tx = tid & 15, ty = tid >> 4;
    int row0 = blockIdx.y * 128, col0 = blockIdx.x * 128;

    for (int k0 = 0; k0 < 512; k0 += 16) {
#pragma unroll
        for (int i = 0; i < 2; i++) {
            int t = tid + i * 256;
            int r = t >> 2, kq = (t & 3) << 2;
            float4 v = *(const float4*)&A[(size_t)(row0 + r) * 512 + k0 + kq];
            As[kq + 0][r] = v.x; As[kq + 1][r] = v.y;
            As[kq + 2][r] = v.z; As[kq + 3][r] = v.w;
        }
#pragma unroll
        for (int i = 0; i < 2; i++) {
            int t = tid + i * 256;
            int kr = t >> 5, nq = (t & 31) << 2;
            *(float4*)&Bs[kr][nq] = *(const float4*)&W[(size_t)(k0 + kr) * N + col0 + nq];
        }
        __syncthreads();
#pragma unroll
        for (int kk = 0; kk < 16; kk++) {
            float a[8], b[8];
            *(float4*)&a[0] = *(float4*)&As[kk][ty * 8];
            *(float4*)&a[4] = *(float4*)&As[kk][ty * 8 + 4];
            *(float4*)&b[0] = *(float4*)&Bs[kk][tx * 8];
            *(float4*)&b[4] = *(float4*)&Bs[kk][tx * 8 + 4];
#pragma unroll
            for (int i = 0; i < 8; i++)
#pragma unroll
                for (int j = 0; j < 8; j++) acc[i][j] += a[i] * b[j];
        }
        __syncthreads();
    }
#pragma unroll
    for (int i = 0; i < 8; i++) {
        int row = row0 + ty * 8 + i;
#pragma unroll
        for (int j = 0; j < 8; j++) {
            int col = col0 + tx * 8 + j;
            dst[(size_t)row * N + col] = acc[i][j] + __ldg(&bias[col]);
        }
    }
}

// Persistent forward GRU scan v2.
// 128 blocks x 256 threads. Block owns 4 h-columns (j0 = blockIdx*4).
// Warp w = K-chunk [w*64, w*64+64), lane = batch b.
// h loaded straight into 64 registers (coalesced __ldcg rows, no SMEM stage).
// Weights: sw[k*12 + gate*4 + jl]; warp-uniform k -> broadcast LDS.128 x3.
__global__ void __launch_bounds__(256) scan_kernel(
    int layer, int bar_base,
    const float* __restrict__ Whh, const float* __restrict__ bhh,
    const float* __restrict__ Whr, const float* __restrict__ bhr)
{
    __shared__ float sw[512 * 12];   // 24 KB persistent weights
    __shared__ float red[8 * 384];   // 12 KB K-split partials
    __shared__ float sb[12];

    const int tid = threadIdx.x;
    const int warp = tid >> 5, lane = tid & 31;
    const int j0 = blockIdx.x * 4;

    for (int i = tid; i < 512 * 12; i += 256) {
        int k = i / 12, idx = i - k * 12;
        int gate = idx >> 2, jl = idx & 3;
        float v;
        if (gate == 0)      v = Whh[k * 1024 + j0 + jl];
        else if (gate == 1) v = Whh[k * 1024 + 512 + j0 + jl];
        else                v = Whr[k * 512 + j0 + jl];
        sw[i] = v;
    }
    if (tid < 12) {
        int gate = tid >> 2, jl = tid & 3;
        sb[tid] = (gate == 0) ? bhh[j0 + jl]
                : (gate == 1) ? bhh[512 + j0 + jl]
                              : bhr[j0 + jl];
    }
    __syncthreads();

    const float* xh = g_xh;
    const float* xr = g_xr;
    float* out = g_out1;
    const int k0 = warp * 64;

    // gating-thread identity (tid < 128): jl_g in [0,4), bb in [0,32)
    const int jl_g = tid >> 5;          // == warp, valid for tid<128
    const int bb = tid & 31;
    const int jg = j0 + jl_g;

    for (int t = 0; t < 128; t++) {
        const float* hcur = g_h + (t & 1) * 16384;
        float* hnxt = g_h + ((t + 1) & 1) * 16384;

        // prefetch gating inputs early (consumed after reduction)
        float pz = 0.f, pr = 0.f, pg = 0.f, hold = 0.f;
        if (tid < 128) {
            int m = bb * 128 + t;
            pz = __ldg(&xh[(size_t)m * 1024 + jg]);
            pr = __ldg(&xh[(size_t)m * 1024 + 512 + jg]);
            pg = __ldg(&xr[(size_t)m * 512 + jg]);
            hold = __ldcg(&hcur[jg * 32 + bb]);
        }

        // load own K-chunk of h into registers (coalesced, bypass L1)
        float hreg[64];
#pragma unroll
        for (int k = 0; k < 64; k++)
            hreg[k] = __ldcg(&hcur[(k0 + k) * 32 + lane]);

        float az0=0,az1=0,az2=0,az3=0, ar0=0,ar1=0,ar2=0,ar3=0;
        float ag0=0,ag1=0,ag2=0,ag3=0;
#pragma unroll
        for (int k = 0; k < 64; k++) {
            const float* wp = &sw[(k0 + k) * 12];
            float4 wz = *(const float4*)wp;        // broadcast
            float4 wr = *(const float4*)(wp + 4);
            float4 wg = *(const float4*)(wp + 8);
            float h = hreg[k];
            az0 += h * wz.x; az1 += h * wz.y; az2 += h * wz.z; az3 += h * wz.w;
            ar0 += h * wr.x; ar1 += h * wr.y; ar2 += h * wr.z; ar3 += h * wr.w;
            ag0 += h * wg.x; ag1 += h * wg.y; ag2 += h * wg.z; ag3 += h * wg.w;
        }
        {
            float* rp = &red[warp * 384 + lane];
            rp[0*32]=az0; rp[1*32]=az1; rp[2*32]=az2;  rp[3*32]=az3;
            rp[4*32]=ar0; rp[5*32]=ar1; rp[6*32]=ar2;  rp[7*32]=ar3;
            rp[8*32]=ag0; rp[9*32]=ag1; rp[10*32]=ag2; rp[11*32]=ag3;
        }
        __syncthreads();

        if (tid < 128) {
            float z = 0.f, r = 0.f, g = 0.f;
#pragma unroll
            for (int s = 0; s < 8; s++) {
                const float* q = &red[s * 384 + bb];
                z += q[jl_g * 32];
                r += q[(4 + jl_g) * 32];
                g += q[(8 + jl_g) * 32];
            }
            z += pz + sb[jl_g];
            r += pr + sb[4 + jl_g];
            float zs = 1.f / (1.f + __expf(-z));
            float rs = 1.f / (1.f + __expf(-r));
            float gg = tanhf((g + sb[8 + jl_g]) * rs + pg);
            float hnew = zs * hold + (1.f - zs) * gg;
            hnxt[jg * 32 + bb] = hnew;
            if (!layer) out[(size_t)(bb * 128 + t) * 512 + jg] = hnew;
        }

        // grid barrier (fence by all threads, arrive+spin by t0)
        __threadfence();
        __syncthreads();
        if (tid == 0) {
            atomicAdd(&g_bar, 1u);
            unsigned need = (unsigned)bar_base + (unsigned)(t + 1) * 128u;
            while (*((volatile unsigned*)&g_bar) < need) __nanosleep(32);
            __threadfence();
        }
        __syncthreads();
    }
}

// One GRU step with h=0 (reverse branch collapses to two of these).
__global__ void __launch_bounds__(512) rev_step(
    const float* __restrict__ Xext, int ldx, int src_sel,
    const float* __restrict__ Wxh, const float* __restrict__ bxh,
    const float* __restrict__ bhh,
    const float* __restrict__ Wxr, const float* __restrict__ bxr,
    const float* __restrict__ bhr, int dst_trans)
{
    __shared__ float xs[256 * 33];
    const float* X = src_sel ? g_hr1 : Xext;
    int tid = threadIdx.x;
    int jl = tid >> 5, b = tid & 31;
    int j = blockIdx.x * 16 + jl;
    float az = 0.f, ar = 0.f, ag = 0.f;

    for (int k0 = 0; k0 < 512; k0 += 256) {
        __syncthreads();
        int half = tid >> 8, kl = tid & 255;
        for (int b2 = half; b2 < 32; b2 += 2)
            xs[kl * 33 + b2] = X[(size_t)b2 * ldx + k0 + kl];
        __syncthreads();
#pragma unroll 8
        for (int k = 0; k < 256; k++) {
            float xv = xs[k * 33 + b];
            int kk = k0 + k;
            az += xv * __ldg(&Wxh[(size_t)kk * 1024 + j]);
            ar += xv * __ldg(&Wxh[(size_t)kk * 1024 + 512 + j]);
            ag += xv * __ldg(&Wxr[(size_t)kk * 512 + j]);
        }
    }
    float z = 1.f / (1.f + __expf(-(az + __ldg(&bxh[j]) + __ldg(&bhh[j]))));
    float r = 1.f / (1.f + __expf(-(ar + __ldg(&bxh[512 + j]) + __ldg(&bhh[512 + j]))));
    float g = tanhf(__ldg(&bhr[j]) * r + ag + __ldg(&bxr[j]));
    float h = (1.f - z) * g;
    if (dst_trans) g_hr2T[j * 32 + b] = h;
    else           g_hr1[b * 512 + j] = h;
}

// out(32,512) = [h_fwd_final | hr2](32,1024) @ Wfc + bfc
__global__ void __launch_bounds__(512) fc_kernel(
    const float* __restrict__ Wfc, const float* __restrict__ bfc,
    float* __restrict__ out)
{
    int tid = threadIdx.x;
    int jl = tid >> 5, b = tid & 31;
    int j = blockIdx.x * 16 + jl;
    float acc = 0.f;
#pragma unroll 4
    for (int k = 0; k < 512; k++)
        acc += g_h[k * 32 + b] * __ldg(&Wfc[(size_t)k * 512 + j]);
#pragma unroll 4
    for (int k = 0; k < 512; k++)
        acc += g_hr2T[k * 32 + b] * __ldg(&Wfc[(size_t)(512 + k) * 512 + j]);
    out[b * 512 + j] = acc + __ldg(&bfc[j]);
}

extern "C" void kernel_launch(void* const* d_in, const int* in_sizes, int n_in,
                              void* d_out, int out_size) {
    const float* x   = (const float*)d_in[0];
    const float* Wxh = (const float*)d_in[1];
    const float* bxh = (const float*)d_in[2];
    const float* Whh = (const float*)d_in[3];
    const float* bhh = (const float*)d_in[4];
    const float* Wxr = (const float*)d_in[5];
    const float* bxr = (const float*)d_in[6];
    const float* Whr = (const float*)d_in[7];
    const float* bhr = (const float*)d_in[8];
    const float* Wfc = (const float*)d_in[9];
    const float* bfc = (const float*)d_in[10];
    float* out = (float*)d_out;

    const size_t WH = 512 * 1024, WR = 512 * 512;

    init_kernel<<<64, 256>>>();

    dim3 g1(8, 32), g2(4, 32);
    // layer 0 forward (slab 0)
    bulk_gemm<<<g1, 256>>>(x, 0, Wxh, bxh, 1024, 0);
    bulk_gemm<<<g2, 256>>>(x, 0, Wxr, bxr, 512, 1);
    scan_kernel<<<128, 256>>>(0, 0, Whh, bhh, Whr, bhr);

    // layer 1 forward (slab 2)
    zero_h_kernel<<<16, 256>>>();
    bulk_gemm<<<g1, 256>>>(nullptr, 1, Wxh + 2 * WH, bxh + 2 * 1024, 1024, 0);
    bulk_gemm<<<g2, 256>>>(nullptr, 1, Wxr + 2 * WR, bxr + 2 * 512, 512, 1);
    scan_kernel<<<128, 256>>>(1, 16384,
        Whh + 2 * WH, bhh + 2 * 1024, Whr + 2 * WR, bhr + 2 * 512);

    // reverse branch: two single steps (slabs 1, 3)
    rev_step<<<32, 512>>>(x + 127 * 512, 128 * 512, 0,
        Wxh + 1 * WH, bxh + 1 * 1024, bhh + 1 * 1024,
        Wxr + 1 * WR, bxr + 1 * 512, bhr + 1 * 512, 0);
    rev_step<<<32, 512>>>(nullptr, 512, 1,
        Wxh + 3 * WH, bxh + 3 * 1024, bhh + 3 * 1024,
        Wxr + 3 * WR, bxr + 3 * 512, bhr + 3 * 512, 1);

    fc_kernel<<<32, 512>>>(Wfc, bfc, out);
}

// round 10
// speedup vs baseline: 1.0761x; 1.0178x over previous
#include <cuda_runtime.h>
#include <math.h>
#include <stdint.h>

// B=32, T=128, I=512, H=512, L=2, O=512
__device__ float g_xh[4096 * 1024];   // input proj zr, row m=b*128+t
__device__ float g_xr[4096 * 512];    // input proj r-gate input
__device__ float g_out1[4096 * 512];  // layer-1 fwd outputs
__device__ float g_h[2 * 16384];      // h double buffer, layout (j, b)
__device__ float g_hr1[32 * 512];     // reverse step1 hidden (b, j)
__device__ float g_hr2T[512 * 32];    // reverse step2 hidden (j, b)
__device__ unsigned g_bar;
__device__ unsigned g_release;

#define FMA2(acc, a, b) \
    asm("fma.rn.f32x2 %0, %1, %2, %0;" : "+l"(acc) : "l"(a), "l"(b))
#define PACK2(dst, lo, hi) \
    asm("mov.b64 %0, {%1, %2};" : "=l"(dst) : "f"(lo), "f"(hi))
#define UNPACK2(lo, hi, src) \
    asm("mov.b64 {%0, %1}, %2;" : "=f"(lo), "=f"(hi) : "l"(src))
#define LDS_V2U64(a, b, addr) \
    asm("ld.shared.v2.u64 {%0, %1}, [%2];" : "=l"(a), "=l"(b) : "r"(addr))

__device__ __forceinline__ uint32_t su32(const void* p) {
    uint32_t a;
    asm("{ .reg .u64 t; cvta.to.shared.u64 t, %1; cvt.u32.u64 %0, t; }"
        : "=r"(a) : "l"(p));
    return a;
}

__global__ void init_kernel() {
    unsigned tid = blockIdx.x * blockDim.x + threadIdx.x;
    if (tid == 0) { g_bar = 0u; g_release = 0u; }
    for (unsigned i = tid; i < 32768u; i += gridDim.x * blockDim.x) g_h[i] = 0.f;
}

__global__ void zero_h_kernel() {
    unsigned tid = blockIdx.x * blockDim.x + threadIdx.x;
    for (unsigned i = tid; i < 16384u; i += gridDim.x * blockDim.x) g_h[i] = 0.f;
}

// C(4096,N) = A(4096,512) @ W(512,N) + bias, f32x2-packed accumulators.
__global__ void __launch_bounds__(256) bulk_gemm(
    const float* __restrict__ Aext, int src_sel,
    const float* __restrict__ W, const float* __restrict__ bias,
    int N, int dst_sel)
{
    __shared__ __align__(16) float As[16][136];
    __shared__ __align__(16) float Bs[16][136];
    const float* A = src_sel ? g_out1 : Aext;
    float* dst = dst_sel ? g_xr : g_xh;

    unsigned long long accp[8][4];
#pragma unroll
    for (int i = 0; i < 8; i++)
#pragma unroll
        for (int j = 0; j < 4; j++) accp[i][j] = 0ULL;

    int tid = threadIdx.x, tx = tid & 15, ty = tid >> 4;
    int row0 = blockIdx.y * 128, col0 = blockIdx.x * 128;
    uint32_t bs_base = su32(&Bs[0][0]);

    for (int k0 = 0; k0 < 512; k0 += 16) {
#pragma unroll
        for (int i = 0; i < 2; i++) {
            int t = tid + i * 256;
            int r = t >> 2, kq = (t & 3) << 2;
            float4 v = *(const float4*)&A[(size_t)(row0 + r) * 512 + k0 + kq];
            As[kq + 0][r] = v.x; As[kq + 1][r] = v.y;
            As[kq + 2][r] = v.z; As[kq + 3][r] = v.w;
        }
#pragma unroll
        for (int i = 0; i < 2; i++) {
            int t = tid + i * 256;
            int kr = t >> 5, nq = (t & 31) << 2;
            *(float4*)&Bs[kr][nq] = *(const float4*)&W[(size_t)(k0 + kr) * N + col0 + nq];
        }
        __syncthreads();
#pragma unroll
        for (int kk = 0; kk < 16; kk++) {
            float a[8];
            *(float4*)&a[0] = *(float4*)&As[kk][ty * 8];
            *(float4*)&a[4] = *(float4*)&As[kk][ty * 8 + 4];
            unsigned long long b01, b23, b45, b67;
            uint32_t ba = bs_base + (uint32_t)(kk * 136 + tx * 8) * 4u;
            LDS_V2U64(b01, b23, ba);
            LDS_V2U64(b45, b67, ba + 16);
#pragma unroll
            for (int i = 0; i < 8; i++) {
                unsigned long long ap;
                PACK2(ap, a[i], a[i]);
                FMA2(accp[i][0], ap, b01);
                FMA2(accp[i][1], ap, b23);
                FMA2(accp[i][2], ap, b45);
                FMA2(accp[i][3], ap, b67);
            }
        }
        __syncthreads();
    }
#pragma unroll
    for (int i = 0; i < 8; i++) {
        int row = row0 + ty * 8 + i;
#pragma unroll
        for (int jp = 0; jp < 4; jp++) {
            float f0, f1;
            UNPACK2(f0, f1, accp[i][jp]);
            int col = col0 + tx * 8 + jp * 2;
            dst[(size_t)row * N + col]     = f0 + __ldg(&bias[col]);
            dst[(size_t)row * N + col + 1] = f1 + __ldg(&bias[col + 1]);
        }
    }
}

// Persistent forward GRU scan v3: f32x2 inner product + cheap grid barrier.
// 128 blocks x 256 threads; block owns 4 h-cols; warp = 64-k chunk, lane = b.
__global__ void __launch_bounds__(256) scan_kernel(
    int layer,
    const float* __restrict__ Whh, const float* __restrict__ bhh,
    const float* __restrict__ Whr, const float* __restrict__ bhr)
{
    __shared__ __align__(16) float sw[512 * 12];   // [k][z0..3,r0..3,g0..3]
    __shared__ __align__(16) float red[8 * 448];   // [warp][lane*14 + 0..11]
    __shared__ float sb[12];

    const int tid = threadIdx.x;
    const int warp = tid >> 5, lane = tid & 31;
    const int j0 = blockIdx.x * 4;
    const unsigned arr_base = (unsigned)layer * 16384u;
    const unsigned rel_base = (unsigned)layer * 128u;

    for (int i = tid; i < 512 * 12; i += 256) {
        int k = i / 12, idx = i - k * 12;
        int gate = idx >> 2, jl = idx & 3;
        float v;
        if (gate == 0)      v = Whh[k * 1024 + j0 + jl];
        else if (gate == 1) v = Whh[k * 1024 + 512 + j0 + jl];
        else                v = Whr[k * 512 + j0 + jl];
        sw[i] = v;
    }
    if (tid < 12) {
        int gate = tid >> 2, jl = tid & 3;
        sb[tid] = (gate == 0) ? bhh[j0 + jl]
                : (gate == 1) ? bhh[512 + j0 + jl]
                              : bhr[j0 + jl];
    }
    __syncthreads();

    const float* xh = g_xh;
    const float* xr = g_xr;
    float* out = g_out1;
    const int k0 = warp * 64;
    const uint32_t swb = su32(sw) + (uint32_t)k0 * 48u;

    const int jl_g = tid >> 5;   // valid for tid<128
    const int bb = tid & 31;
    const int jg = j0 + jl_g;

    for (int t = 0; t < 128; t++) {
        const float* hcur = g_h + (t & 1) * 16384;
        float* hnxt = g_h + ((t + 1) & 1) * 16384;

        // prefetch gating inputs (consumed after reduction)
        float pz = 0.f, pr = 0.f, pg = 0.f, hold = 0.f;
        if (tid < 128) {
            int m = bb * 128 + t;
            pz = __ldg(&xh[(size_t)m * 1024 + jg]);
            pr = __ldg(&xh[(size_t)m * 1024 + 512 + jg]);
            pg = __ldg(&xr[(size_t)m * 512 + jg]);
            hold = __ldcg(&hcur[jg * 32 + bb]);
        }

        // own K-chunk of h, coalesced, bypass L1
        float hreg[64];
#pragma unroll
        for (int k = 0; k < 64; k++)
            hreg[k] = __ldcg(&hcur[(k0 + k) * 32 + lane]);

        unsigned long long az01 = 0, az23 = 0, ar01 = 0, ar23 = 0;
        unsigned long long ag01 = 0, ag23 = 0;
#pragma unroll
        for (int k = 0; k < 64; k++) {
            float h = hreg[k];
            unsigned long long hh;
            PACK2(hh, h, h);
            unsigned long long wz01, wz23, wr01, wr23, wg01, wg23;
            uint32_t a = swb + (uint32_t)k * 48u;
            LDS_V2U64(wz01, wz23, a);
            LDS_V2U64(wr01, wr23, a + 16);
            LDS_V2U64(wg01, wg23, a + 32);
            FMA2(az01, wz01, hh); FMA2(az23, wz23, hh);
            FMA2(ar01, wr01, hh); FMA2(ar23, wr23, hh);
            FMA2(ag01, wg01, hh); FMA2(ag23, wg23, hh);
        }
        {
            unsigned long long* rp =
                (unsigned long long*)&red[warp * 448 + lane * 14];
            rp[0] = az01; rp[1] = az23;
            rp[2] = ar01; rp[3] = ar23;
            rp[4] = ag01; rp[5] = ag23;
        }
        __syncthreads();

        if (tid < 128) {
            float z = 0.f, r = 0.f, g = 0.f;
#pragma unroll
            for (int s = 0; s < 8; s++) {
                const float* q = &red[s * 448 + bb * 14];
                z += q[jl_g];
                r += q[4 + jl_g];
                g += q[8 + jl_g];
            }
            z += pz + sb[jl_g];
            r += pr + sb[4 + jl_g];
            float zs = 1.f / (1.f + __expf(-z));
            float rs = 1.f / (1.f + __expf(-r));
            float gg = tanhf((g + sb[8 + jl_g]) * rs + pg);
            float hnew = zs * hold + (1.f - zs) * gg;
            hnxt[jg * 32 + bb] = hnew;
            if (!layer) out[(size_t)(bb * 128 + t) * 512 + jg] = hnew;
        }

        // grid barrier: CTA bar orders stores; one thread fences + signals;
        // last arriver publishes release flag; others poll read-only flag.
        __syncthreads();
        if (tid == 0) {
            __threadfence();
            unsigned old = atomicAdd(&g_bar, 1u);
            unsigned target = rel_base + (unsigned)(t + 1);
            if (old == arr_base + (unsigned)t * 128u + 127u) {
                __threadfence();
                *(volatile unsigned*)&g_release = target;
            } else {
                while (*(volatile unsigned*)&g_release < target) { }
            }
            __threadfence();
        }
        __syncthreads();
    }
}

// One GRU step with h=0 (reverse branch collapses to two of these).
__global__ void __launch_bounds__(512) rev_step(
    const float* __restrict__ Xext, int ldx, int src_sel,
    const float* __restrict__ Wxh, const float* __restrict__ bxh,
    const float* __restrict__ bhh,
    const float* __restrict__ Wxr, const float* __restrict__ bxr,
    const float* __restrict__ bhr, int dst_trans)
{
    __shared__ float xs[256 * 33];
    const float* X = src_sel ? g_hr1 : Xext;
    int tid = threadIdx.x;
    int jl = tid >> 5, b = tid & 31;
    int j = blockIdx.x * 16 + jl;
    float az = 0.f, ar = 0.f, ag = 0.f;

    for (int k0 = 0; k0 < 512; k0 += 256) {
        __syncthreads();
        int half = tid >> 8, kl = tid & 255;
        for (int b2 = half; b2 < 32; b2 += 2)
            xs[kl * 33 + b2] = X[(size_t)b2 * ldx + k0 + kl];
        __syncthreads();
#pragma unroll 8
        for (int k = 0; k < 256; k++) {
            float xv = xs[k * 33 + b];
            int kk = k0 + k;
            az += xv * __ldg(&Wxh[(size_t)kk * 1024 + j]);
            ar += xv * __ldg(&Wxh[(size_t)kk * 1024 + 512 + j]);
            ag += xv * __ldg(&Wxr[(size_t)kk * 512 + j]);
        }
    }
    float z = 1.f / (1.f + __expf(-(az + __ldg(&bxh[j]) + __ldg(&bhh[j]))));
    float r = 1.f / (1.f + __expf(-(ar + __ldg(&bxh[512 + j]) + __ldg(&bhh[512 + j]))));
    float g = tanhf(__ldg(&bhr[j]) * r + ag + __ldg(&bxr[j]));
    float h = (1.f - z) * g;
    if (dst_trans) g_hr2T[j * 32 + b] = h;
    else           g_hr1[b * 512 + j] = h;
}

// out(32,512) = [h_fwd_final | hr2](32,1024) @ Wfc + bfc
__global__ void __launch_bounds__(512) fc_kernel(
    const float* __restrict__ Wfc, const float* __restrict__ bfc,
    float* __restrict__ out)
{
    int tid = threadIdx.x;
    int jl = tid >> 5, b = tid & 31;
    int j = blockIdx.x * 16 + jl;
    float acc = 0.f;
#pragma unroll 4
    for (int k = 0; k < 512; k++)
        acc += g_h[k * 32 + b] * __ldg(&Wfc[(size_t)k * 512 + j]);
#pragma unroll 4
    for (int k = 0; k < 512; k++)
        acc += g_hr2T[k * 32 + b] * __ldg(&Wfc[(size_t)(512 + k) * 512 + j]);
    out[b * 512 + j] = acc + __ldg(&bfc[j]);
}

extern "C" void kernel_launch(void* const* d_in, const int* in_sizes, int n_in,
                              void* d_out, int out_size) {
    const float* x   = (const float*)d_in[0];
    const float* Wxh = (const float*)d_in[1];
    const float* bxh = (const float*)d_in[2];
    const float* Whh = (const float*)d_in[3];
    const float* bhh = (const float*)d_in[4];
    const float* Wxr = (const float*)d_in[5];
    const float* bxr = (const float*)d_in[6];
    const float* Whr = (const float*)d_in[7];
    const float* bhr = (const float*)d_in[8];
    const float* Wfc = (const float*)d_in[9];
    const float* bfc = (const float*)d_in[10];
    float* out = (float*)d_out;

    const size_t WH = 512 * 1024, WR = 512 * 512;

    init_kernel<<<64, 256>>>();

    dim3 g1(8, 32), g2(4, 32);
    // layer 0 forward (slab 0)
    bulk_gemm<<<g1, 256>>>(x, 0, Wxh, bxh, 1024, 0);
    bulk_gemm<<<g2, 256>>>(x, 0, Wxr, bxr, 512, 1);
    scan_kernel<<<128, 256>>>(0, Whh, bhh, Whr, bhr);

    // layer 1 forward (slab 2)
    zero_h_kernel<<<16, 256>>>();
    bulk_gemm<<<g1, 256>>>(nullptr, 1, Wxh + 2 * WH, bxh + 2 * 1024, 1024, 0);
    bulk_gemm<<<g2, 256>>>(nullptr, 1, Wxr + 2 * WR, bxr + 2 * 512, 512, 1);
    scan_kernel<<<128, 256>>>(1,
        Whh + 2 * WH, bhh + 2 * 1024, Whr + 2 * WR, bhr + 2 * 512);

    // reverse branch: two single steps (slabs 1, 3)
    rev_step<<<32, 512>>>(x + 127 * 512, 128 * 512, 0,
        Wxh + 1 * WH, bxh + 1 * 1024, bhh + 1 * 1024,
        Wxr + 1 * WR, bxr + 1 * 512, bhr + 1 * 512, 0);
    rev_step<<<32, 512>>>(nullptr, 512, 1,
        Wxh + 3 * WH, bxh + 3 * 1024, bhh + 3 * 1024,
        Wxr + 3 * WR, bxr + 3 * 512, bhr + 3 * 512, 1);

    fc_kernel<<<32, 512>>>(Wfc, bfc, out);
}

// round 11
// speedup vs baseline: 1.2282x; 1.1414x over previous
#include <cuda_runtime.h>
#include <math.h>
#include <stdint.h>

// B=32, T=128, I=512, H=512, L=2, O=512
__device__ float g_xh[4096 * 1024];   // input proj zr, row m=b*128+t
__device__ float g_xr[4096 * 512];    // input proj r-gate input
__device__ float g_out1[4096 * 512];  // layer-1 fwd outputs
__device__ float g_h[2 * 16384];      // h double buffer, layout (j, b)
__device__ float g_hr1[32 * 512];     // reverse step1 hidden (b, j)
__device__ float g_hr2T[512 * 32];    // reverse step2 hidden (j, b)
__device__ unsigned g_flags[128 * 32];  // per-CTA barrier flags (own line each)

#define FMA2(acc, a, b) \
    asm("fma.rn.f32x2 %0, %1, %2, %0;" : "+l"(acc) : "l"(a), "l"(b))
#define PACK2(dst, lo, hi) \
    asm("mov.b64 %0, {%1, %2};" : "=l"(dst) : "f"(lo), "f"(hi))
#define UNPACK2(lo, hi, src) \
    asm("mov.b64 {%0, %1}, %2;" : "=f"(lo), "=f"(hi) : "l"(src))
#define LDS_V2U64(a, b, addr) \
    asm("ld.shared.v2.u64 {%0, %1}, [%2];" : "=l"(a), "=l"(b) : "r"(addr))

__device__ __forceinline__ uint32_t su32(const void* p) {
    uint32_t a;
    asm("{ .reg .u64 t; cvta.to.shared.u64 t, %1; cvt.u32.u64 %0, t; }"
        : "=r"(a) : "l"(p));
    return a;
}
__device__ __forceinline__ unsigned ld_acq(const unsigned* p) {
    unsigned v;
    asm volatile("ld.acquire.gpu.u32 %0, [%1];" : "=r"(v) : "l"(p));
    return v;
}
__device__ __forceinline__ void st_rel(unsigned* p, unsigned v) {
    asm volatile("st.release.gpu.u32 [%0], %1;" :: "l"(p), "r"(v));
}

__global__ void init_kernel() {
    unsigned tid = blockIdx.x * blockDim.x + threadIdx.x;
    for (unsigned i = tid; i < 32768u; i += gridDim.x * blockDim.x) g_h[i] = 0.f;
    for (unsigned i = tid; i < 4096u; i += gridDim.x * blockDim.x) g_flags[i] = 0u;
}

__global__ void zero_h_kernel() {
    unsigned tid = blockIdx.x * blockDim.x + threadIdx.x;
    for (unsigned i = tid; i < 16384u; i += gridDim.x * blockDim.x) g_h[i] = 0.f;
}

// C(4096,N) = A(4096,512) @ W(512,N) + bias, f32x2-packed accumulators.
__global__ void __launch_bounds__(256) bulk_gemm(
    const float* __restrict__ Aext, int src_sel,
    const float* __restrict__ W, const float* __restrict__ bias,
    int N, int dst_sel)
{
    __shared__ __align__(16) float As[16][136];
    __shared__ __align__(16) float Bs[16][136];
    const float* A = src_sel ? g_out1 : Aext;
    float* dst = dst_sel ? g_xr : g_xh;

    unsigned long long accp[8][4];
#pragma unroll
    for (int i = 0; i < 8; i++)
#pragma unroll
        for (int j = 0; j < 4; j++) accp[i][j] = 0ULL;

    int tid = threadIdx.x, tx = tid & 15, ty = tid >> 4;
    int row0 = blockIdx.y * 128, col0 = blockIdx.x * 128;
    uint32_t bs_base = su32(&Bs[0][0]);

    for (int k0 = 0; k0 < 512; k0 += 16) {
#pragma unroll
        for (int i = 0; i < 2; i++) {
            int t = tid + i * 256;
            int r = t >> 2, kq = (t & 3) << 2;
            float4 v = *(const float4*)&A[(size_t)(row0 + r) * 512 + k0 + kq];
            As[kq + 0][r] = v.x; As[kq + 1][r] = v.y;
            As[kq + 2][r] = v.z; As[kq + 3][r] = v.w;
        }
#pragma unroll
        for (int i = 0; i < 2; i++) {
            int t = tid + i * 256;
            int kr = t >> 5, nq = (t & 31) << 2;
            *(float4*)&Bs[kr][nq] = *(const float4*)&W[(size_t)(k0 + kr) * N + col0 + nq];
        }
        __syncthreads();
#pragma unroll
        for (int kk = 0; kk < 16; kk++) {
            float a[8];
            *(float4*)&a[0] = *(float4*)&As[kk][ty * 8];
            *(float4*)&a[4] = *(float4*)&As[kk][ty * 8 + 4];
            unsigned long long b01, b23, b45, b67;
            uint32_t ba = bs_base + (uint32_t)(kk * 136 + tx * 8) * 4u;
            LDS_V2U64(b01, b23, ba);
            LDS_V2U64(b45, b67, ba + 16);
#pragma unroll
            for (int i = 0; i < 8; i++) {
                unsigned long long ap;
                PACK2(ap, a[i], a[i]);
                FMA2(accp[i][0], ap, b01);
                FMA2(accp[i][1], ap, b23);
                FMA2(accp[i][2], ap, b45);
                FMA2(accp[i][3], ap, b67);
            }
        }
        __syncthreads();
    }
#pragma unroll
    for (int i = 0; i < 8; i++) {
        int row = row0 + ty * 8 + i;
#pragma unroll
        for (int jp = 0; jp < 4; jp++) {
            float f0, f1;
            UNPACK2(f0, f1, accp[i][jp]);
            int col = col0 + tx * 8 + jp * 2;
            dst[(size_t)row * N + col]     = f0 + __ldg(&bias[col]);
            dst[(size_t)row * N + col + 1] = f1 + __ldg(&bias[col + 1]);
        }
    }
}

// Persistent forward GRU scan v4: f32x2 inner product + distributed-flag
// grid barrier (no atomics: 1 release store per CTA, 128 parallel acquire
// polls on distinct lines).
__global__ void __launch_bounds__(256) scan_kernel(
    int layer,
    const float* __restrict__ Whh, const float* __restrict__ bhh,
    const float* __restrict__ Whr, const float* __restrict__ bhr)
{
    __shared__ __align__(16) float sw[512 * 12];   // [k][z0..3,r0..3,g0..3]
    __shared__ __align__(16) float red[8 * 448];   // [warp][lane*14 + 0..11]
    __shared__ float sb[12];

    const int tid = threadIdx.x;
    const int warp = tid >> 5, lane = tid & 31;
    const int j0 = blockIdx.x * 4;
    const unsigned step_base = (unsigned)layer * 128u;

    for (int i = tid; i < 512 * 12; i += 256) {
        int k = i / 12, idx = i - k * 12;
        int gate = idx >> 2, jl = idx & 3;
        float v;
        if (gate == 0)      v = Whh[k * 1024 + j0 + jl];
        else if (gate == 1) v = Whh[k * 1024 + 512 + j0 + jl];
        else                v = Whr[k * 512 + j0 + jl];
        sw[i] = v;
    }
    if (tid < 12) {
        int gate = tid >> 2, jl = tid & 3;
        sb[tid] = (gate == 0) ? bhh[j0 + jl]
                : (gate == 1) ? bhh[512 + j0 + jl]
                              : bhr[j0 + jl];
    }
    __syncthreads();

    const float* xh = g_xh;
    const float* xr = g_xr;
    float* out = g_out1;
    const int k0 = warp * 64;
    const uint32_t swb = su32(sw) + (uint32_t)k0 * 48u;

    const int jl_g = tid >> 5;   // valid for tid<128
    const int bb = tid & 31;
    const int jg = j0 + jl_g;
    unsigned* myflag = &g_flags[blockIdx.x * 32];
    const unsigned* pollflag = &g_flags[(tid & 127) * 32];

    for (int t = 0; t < 128; t++) {
        const float* hcur = g_h + (t & 1) * 16384;
        float* hnxt = g_h + ((t + 1) & 1) * 16384;

        // prefetch gating inputs (consumed after reduction)
        float pz = 0.f, pr = 0.f, pg = 0.f, hold = 0.f;
        if (tid < 128) {
            int m = bb * 128 + t;
            pz = __ldg(&xh[(size_t)m * 1024 + jg]);
            pr = __ldg(&xh[(size_t)m * 1024 + 512 + jg]);
            pg = __ldg(&xr[(size_t)m * 512 + jg]);
            hold = __ldcg(&hcur[jg * 32 + bb]);
        }

        // own K-chunk of h, coalesced, bypass L1
        float hreg[64];
#pragma unroll
        for (int k = 0; k < 64; k++)
            hreg[k] = __ldcg(&hcur[(k0 + k) * 32 + lane]);

        unsigned long long az01 = 0, az23 = 0, ar01 = 0, ar23 = 0;
        unsigned long long ag01 = 0, ag23 = 0;
#pragma unroll
        for (int k = 0; k < 64; k++) {
            float h = hreg[k];
            unsigned long long hh;
            PACK2(hh, h, h);
            unsigned long long wz01, wz23, wr01, wr23, wg01, wg23;
            uint32_t a = swb + (uint32_t)k * 48u;
            LDS_V2U64(wz01, wz23, a);
            LDS_V2U64(wr01, wr23, a + 16);
            LDS_V2U64(wg01, wg23, a + 32);
            FMA2(az01, wz01, hh); FMA2(az23, wz23, hh);
            FMA2(ar01, wr01, hh); FMA2(ar23, wr23, hh);
            FMA2(ag01, wg01, hh); FMA2(ag23, wg23, hh);
        }
        {
            unsigned long long* rp =
                (unsigned long long*)&red[warp * 448 + lane * 14];
            rp[0] = az01; rp[1] = az23;
            rp[2] = ar01; rp[3] = ar23;
            rp[4] = ag01; rp[5] = ag23;
        }
        __syncthreads();

        if (tid < 128) {
            float z = 0.f, r = 0.f, g = 0.f;
#pragma unroll
            for (int s = 0; s < 8; s++) {
                const float* q = &red[s * 448 + bb * 14];
                z += q[jl_g];
                r += q[4 + jl_g];
                g += q[8 + jl_g];
            }
            z += pz + sb[jl_g];
            r += pr + sb[4 + jl_g];
            float zs = 1.f / (1.f + __expf(-z));
            float rs = 1.f / (1.f + __expf(-r));
            float gg = tanhf((g + sb[8 + jl_g]) * rs + pg);
            float hnew = zs * hold + (1.f - zs) * gg;
            hnxt[jg * 32 + bb] = hnew;
            if (!layer) out[(size_t)(bb * 128 + t) * 512 + jg] = hnew;
        }

        // distributed-flag grid barrier:
        //  bar.sync orders the CTA's h stores; thread 0's st.release.gpu is
        //  cumulative (includes them); 128 threads acquire-poll 128 distinct
        //  flag lines in parallel; bar.sync joins the acquires for the CTA.
        unsigned target = step_base + (unsigned)(t + 1);
        __syncthreads();
        if (tid == 0) st_rel(myflag, target);
        if (tid < 128) {
            while (ld_acq(pollflag) < target) { }
        }
        __syncthreads();
    }
}

// One GRU step with h=0 (reverse branch collapses to two of these).
__global__ void __launch_bounds__(512) rev_step(
    const float* __restrict__ Xext, int ldx, int src_sel,
    const float* __restrict__ Wxh, const float* __restrict__ bxh,
    const float* __restrict__ bhh,
    const float* __restrict__ Wxr, const float* __restrict__ bxr,
    const float* __restrict__ bhr, int dst_trans)
{
    __shared__ float xs[256 * 33];
    const float* X = src_sel ? g_hr1 : Xext;
    int tid = threadIdx.x;
    int jl = tid >> 5, b = tid & 31;
    int j = blockIdx.x * 16 + jl;
    float az = 0.f, ar = 0.f, ag = 0.f;

    for (int k0 = 0; k0 < 512; k0 += 256) {
        __syncthreads();
        int half = tid >> 8, kl = tid & 255;
        for (int b2 = half; b2 < 32; b2 += 2)
            xs[kl * 33 + b2] = X[(size_t)b2 * ldx + k0 + kl];
        __syncthreads();
#pragma unroll 8
        for (int k = 0; k < 256; k++) {
            float xv = xs[k * 33 + b];
            int kk = k0 + k;
            az += xv * __ldg(&Wxh[(size_t)kk * 1024 + j]);
            ar += xv * __ldg(&Wxh[(size_t)kk * 1024 + 512 + j]);
            ag += xv * __ldg(&Wxr[(size_t)kk * 512 + j]);
        }
    }
    float z = 1.f / (1.f + __expf(-(az + __ldg(&bxh[j]) + __ldg(&bhh[j]))));
    float r = 1.f / (1.f + __expf(-(ar + __ldg(&bxh[512 + j]) + __ldg(&bhh[512 + j]))));
    float g = tanhf(__ldg(&bhr[j]) * r + ag + __ldg(&bxr[j]));
    float h = (1.f - z) * g;
    if (dst_trans) g_hr2T[j * 32 + b] = h;
    else           g_hr1[b * 512 + j] = h;
}

// out(32,512) = [h_fwd_final | hr2](32,1024) @ Wfc + bfc
__global__ void __launch_bounds__(512) fc_kernel(
    const float* __restrict__ Wfc, const float* __restrict__ bfc,
    float* __restrict__ out)
{
    int tid = threadIdx.x;
    int jl = tid >> 5, b = tid & 31;
    int j = blockIdx.x * 16 + jl;
    float acc = 0.f;
#pragma unroll 4
    for (int k = 0; k < 512; k++)
        acc += g_h[k * 32 + b] * __ldg(&Wfc[(size_t)k * 512 + j]);
#pragma unroll 4
    for (int k = 0; k < 512; k++)
        acc += g_hr2T[k * 32 + b] * __ldg(&Wfc[(size_t)(512 + k) * 512 + j]);
    out[b * 512 + j] = acc + __ldg(&bfc[j]);
}

extern "C" void kernel_launch(void* const* d_in, const int* in_sizes, int n_in,
                              void* d_out, int out_size) {
    const float* x   = (const float*)d_in[0];
    const float* Wxh = (const float*)d_in[1];
    const float* bxh = (const float*)d_in[2];
    const float* Whh = (const float*)d_in[3];
    const float* bhh = (const float*)d_in[4];
    const float* Wxr = (const float*)d_in[5];
    const float* bxr = (const float*)d_in[6];
    const float* Whr = (const float*)d_in[7];
    const float* bhr = (const float*)d_in[8];
    const float* Wfc = (const float*)d_in[9];
    const float* bfc = (const float*)d_in[10];
    float* out = (float*)d_out;

    const size_t WH = 512 * 1024, WR = 512 * 512;

    init_kernel<<<64, 256>>>();

    dim3 g1(8, 32), g2(4, 32);
    // layer 0 forward (slab 0)
    bulk_gemm<<<g1, 256>>>(x, 0, Wxh, bxh, 1024, 0);
    bulk_gemm<<<g2, 256>>>(x, 0, Wxr, bxr, 512, 1);
    scan_kernel<<<128, 256>>>(0, Whh, bhh, Whr, bhr);

    // layer 1 forward (slab 2)
    zero_h_kernel<<<16, 256>>>();
    bulk_gemm<<<g1, 256>>>(nullptr, 1, Wxh + 2 * WH, bxh + 2 * 1024, 1024, 0);
    bulk_gemm<<<g2, 256>>>(nullptr, 1, Wxr + 2 * WR, bxr + 2 * 512, 512, 1);
    scan_kernel<<<128, 256>>>(1,
        Whh + 2 * WH, bhh + 2 * 1024, Whr + 2 * WR, bhr + 2 * 512);

    // reverse branch: two single steps (slabs 1, 3)
    rev_step<<<32, 512>>>(x + 127 * 512, 128 * 512, 0,
        Wxh + 1 * WH, bxh + 1 * 1024, bhh + 1 * 1024,
        Wxr + 1 * WR, bxr + 1 * 512, bhr + 1 * 512, 0);
    rev_step<<<32, 512>>>(nullptr, 512, 1,
        Wxh + 3 * WH, bxh + 3 * 1024, bhh + 3 * 1024,
        Wxr + 3 * WR, bxr + 3 * 512, bhr + 3 * 512, 1);

    fc_kernel<<<32, 512>>>(Wfc, bfc, out);
}